// round 6
// baseline (speedup 1.0000x reference)
#include <cuda_runtime.h>
#include <cuda_fp16.h>
#include <cstdint>
#include <cstddef>

// Problem: B=16, T=960, D=1024, W=10
#define DDIM  1024
#define WWIN  10
#define MTOT  15360          // B*T
#define KCONV 3072           // 3*D

static constexpr size_t XSZ = (size_t)MTOT * DDIM;
static constexpr size_t WSZ = (size_t)DDIM * KCONV;
static constexpr size_t GSZ = (size_t)DDIM * DDIM;

// Device scratch (allocation-free rules)
__device__ __half  g_x1[XSZ];      // x fp16, [m][c]
__device__ __half  g_w1[WSZ];      // conv w fp16, [n][k=s*1024+c]
__device__ __half  g_g1[GSZ];      // gate w fp16, [e][d]
__device__ __half  g_c1[XSZ];      // cnn fp16, [m][d]

// ------------------------------------------------------------------ PTX helpers
__device__ __forceinline__ uint32_t smem_u32(const void* p) {
    uint32_t a;
    asm("{ .reg .u64 t; cvta.to.shared.u64 t, %1; cvt.u32.u64 %0, t; }" : "=r"(a) : "l"(p));
    return a;
}
__device__ __forceinline__ void cp16(uint32_t dst, const void* src, uint32_t sz) {
    asm volatile("cp.async.cg.shared.global [%0], [%1], 16, %2;"
                 :: "r"(dst), "l"(src), "r"(sz) : "memory");
}
__device__ __forceinline__ void cp_commit() {
    asm volatile("cp.async.commit_group;" ::: "memory");
}
template <int N>
__device__ __forceinline__ void cp_wait() {
    asm volatile("cp.async.wait_group %0;" :: "n"(N) : "memory");
}
__device__ __forceinline__ void ldsm4(uint32_t* r, uint32_t addr) {
    asm volatile("ldmatrix.sync.aligned.m8n8.x4.shared.b16 {%0,%1,%2,%3}, [%4];"
                 : "=r"(r[0]), "=r"(r[1]), "=r"(r[2]), "=r"(r[3]) : "r"(addr));
}
__device__ __forceinline__ void mma16816(float* d, const uint32_t* a, const uint32_t* b) {
    asm volatile("mma.sync.aligned.m16n8k16.row.col.f32.f16.f16.f32 "
                 "{%0,%1,%2,%3}, {%4,%5,%6,%7}, {%8,%9}, {%0,%1,%2,%3};"
                 : "+f"(d[0]), "+f"(d[1]), "+f"(d[2]), "+f"(d[3])
                 : "r"(a[0]), "r"(a[1]), "r"(a[2]), "r"(a[3]), "r"(b[0]), "r"(b[1]));
}
__device__ __forceinline__ uint32_t pack_h2(float a, float b) {
    return (uint32_t)__half_as_ushort(__float2half_rn(a)) |
           ((uint32_t)__half_as_ushort(__float2half_rn(b)) << 16);
}

// ------------------------------------------------------------------ preprocessing
__global__ void k_split_x(const float* __restrict__ x) {
    size_t i = ((size_t)blockIdx.x * 256 + threadIdx.x) * 4;
    float4 v = *reinterpret_cast<const float4*>(x + i);
    uint2 uh;
    uh.x = pack_h2(v.x, v.y); uh.y = pack_h2(v.z, v.w);
    *reinterpret_cast<uint2*>(g_x1 + i) = uh;
}
__global__ void k_split_convw(const float* __restrict__ w) {
    size_t i = (size_t)blockIdx.x * 256 + threadIdx.x;   // over WSZ, out layout [n][s*1024+c]
    int n = (int)(i / KCONV);
    int k = (int)(i - (size_t)n * KCONV);
    int s = k >> 10, c = k & (DDIM - 1);
    g_w1[i] = __float2half_rn(w[(size_t)n * KCONV + c * 3 + s]);
}
__global__ void k_split_gatew(const float* __restrict__ gw) {
    size_t i = ((size_t)blockIdx.x * 256 + threadIdx.x) * 4;
    float4 v = *reinterpret_cast<const float4*>(gw + i);
    uint2 uh;
    uh.x = pack_h2(v.x, v.y); uh.y = pack_h2(v.z, v.w);
    *reinterpret_cast<uint2*>(g_g1 + i) = uh;
}

// ------------------------------------------------------------------ main GEMM
// CTA 128(M) x 256(N), BK=64 fp16. Stage [A 16KB | B 32KB] = 48KB; 4-stage ring
// = 192KB smem, occ 1. 8 warps in 2(M) x 4(N), warp tile 64x64 (128 acc regs).
static constexpr int PL_A = 0, PL_B = 16384;
static constexpr int STSZ = 49152;
static constexpr int SMEM_SZ = 4 * STSZ;   // 192 KB

template <int CHUNKS, bool IS_CONV>
__global__ __launch_bounds__(256, 1)
void k_mma(const float* __restrict__ bias, float* __restrict__ out) {
    extern __shared__ char smem[];
    const uint32_t sb = smem_u32(smem);

    const int tid = threadIdx.x;
    const int m0 = blockIdx.y * 128, n0 = blockIdx.x * 256;
    const int lane = tid & 31, w = tid >> 5;
    const int wm = w >> 2, wn = w & 3;          // warp grid 2(M) x 4(N)
    const int li = lane & 7, lg = lane >> 3;

    // A loader: 2 threads/row, 4 of 8 16B segs.  B loader: 1 thread/row, 8 segs.
    const int lrA = tid >> 1;
    const int lhA = (tid & 1) * 4;
    const int am = m0 + lrA;
    const int amw = am % WWIN;

    auto load_chunk = [&](int c, int stage) {
        const uint32_t base = sb + stage * STSZ;
        const __half* Ap;
        const __half* Bp;
        uint32_t asz = 16;
        if (IS_CONV) {
            const int s = c >> 4, dt = s - 1, kc = (c & 15) << 6;
            const bool valid = ((unsigned)(amw + dt)) < (unsigned)WWIN;
            asz = valid ? 16u : 0u;
            Ap = g_x1 + (size_t)(valid ? (am + dt) : am) * DDIM + kc;
            Bp = g_w1 + (size_t)(n0 + tid) * KCONV + (c << 6);
        } else {
            Ap = g_c1 + (size_t)am * DDIM + (c << 6);
            Bp = g_g1 + (size_t)(n0 + tid) * DDIM + (c << 6);
        }
#pragma unroll
        for (int j = 0; j < 4; ++j) {
            const int cc = lhA + j;
            cp16(base + PL_A + lrA * 128 + ((cc ^ (lrA & 7)) * 16), Ap + cc * 8, asz);
        }
#pragma unroll
        for (int cc = 0; cc < 8; ++cc) {
            cp16(base + PL_B + tid * 128 + ((cc ^ (tid & 7)) * 16), Bp + cc * 8, 16);
        }
        cp_commit();
    };

    float acc[4][8][4];
#pragma unroll
    for (int i = 0; i < 4; ++i)
#pragma unroll
        for (int j = 0; j < 8; ++j)
#pragma unroll
            for (int q = 0; q < 4; ++q) acc[i][j][q] = 0.f;

    load_chunk(0, 0);
    if (CHUNKS > 1) load_chunk(1, 1);
    if (CHUNKS > 2) load_chunk(2, 2);

    for (int it = 0; it < CHUNKS; ++it) {
        const int stage = it & 3;
        if (it + 3 <= CHUNKS)      cp_wait<2>();
        else if (it + 2 <= CHUNKS) cp_wait<1>();
        else                       cp_wait<0>();
        __syncthreads();
        if (it + 3 < CHUNKS) load_chunk(it + 3, (it + 3) & 3);

        const uint32_t bb = sb + stage * STSZ;
#pragma unroll
        for (int ks = 0; ks < 4; ++ks) {
            uint32_t Bf[4][4];
#pragma unroll
            for (int nt2 = 0; nt2 < 4; ++nt2) {
                const int br = wn * 64 + nt2 * 16 + li + (lg >> 1) * 8;
                const uint32_t cx = (uint32_t)((ks * 2 + (lg & 1)) ^ li);
                ldsm4(Bf[nt2], bb + PL_B + br * 128 + cx * 16);
            }
#pragma unroll
            for (int mt = 0; mt < 4; ++mt) {
                const int ar = wm * 64 + mt * 16 + li + (lg & 1) * 8;
                const uint32_t cx = (uint32_t)((ks * 2 + (lg >> 1)) ^ li);
                uint32_t Af[4];
                ldsm4(Af, bb + PL_A + ar * 128 + cx * 16);
#pragma unroll
                for (int nt = 0; nt < 8; ++nt) {
                    const uint32_t b2[2] = {Bf[nt >> 1][(nt & 1) * 2],
                                            Bf[nt >> 1][(nt & 1) * 2 + 1]};
                    mma16816(acc[mt][nt], Af, b2);
                }
            }
        }
    }

    // ---- epilogue (direct from fragments; cnn kept in fp16 only)
#pragma unroll
    for (int mt = 0; mt < 4; ++mt) {
#pragma unroll
        for (int nt = 0; nt < 8; ++nt) {
            const int gn = n0 + wn * 64 + nt * 8 + (lane & 3) * 2;
            const float b0 = bias[gn], b1 = bias[gn + 1];
#pragma unroll
            for (int hh = 0; hh < 2; ++hh) {
                const int gm = m0 + wm * 64 + mt * 16 + (lane >> 2) + hh * 8;
                float v0 = acc[mt][nt][hh * 2 + 0] + b0;
                float v1 = acc[mt][nt][hh * 2 + 1] + b1;
                const size_t off = (size_t)gm * DDIM + gn;
                if (IS_CONV) {
                    *reinterpret_cast<uint32_t*>(g_c1 + off) = pack_h2(v0, v1);
                } else {
                    const __half2 ch = *reinterpret_cast<const __half2*>(g_c1 + off);
                    const float2 cv = __half22float2(ch);
                    float2 o;
                    o.x = cv.x * (1.f / (1.f + __expf(-v0)));
                    o.y = cv.y * (1.f / (1.f + __expf(-v1)));
                    *reinterpret_cast<float2*>(out + off) = o;
                }
            }
        }
    }
}

// ------------------------------------------------------------------ launch
extern "C" void kernel_launch(void* const* d_in, const int* in_sizes, int n_in,
                              void* d_out, int out_size) {
    const float* x      = (const float*)d_in[0];
    const float* conv_w = (const float*)d_in[1];
    const float* conv_b = (const float*)d_in[2];
    const float* gate_w = (const float*)d_in[3];
    const float* gate_b = (const float*)d_in[4];
    float* out = (float*)d_out;

    cudaFuncSetAttribute(k_mma<48, true>,  cudaFuncAttributeMaxDynamicSharedMemorySize, SMEM_SZ);
    cudaFuncSetAttribute(k_mma<16, false>, cudaFuncAttributeMaxDynamicSharedMemorySize, SMEM_SZ);

    k_split_x<<<(int)(XSZ / 1024), 256>>>(x);
    k_split_convw<<<(int)(WSZ / 256), 256>>>(conv_w);
    k_split_gatew<<<(int)(GSZ / 1024), 256>>>(gate_w);

    dim3 grid(DDIM / 256, MTOT / 128);   // (4, 120)
    k_mma<48, true><<<grid, 256, SMEM_SZ>>>(conv_b, nullptr);
    k_mma<16, false><<<grid, 256, SMEM_SZ>>>(gate_b, out);
}

// round 7
// speedup vs baseline: 1.4692x; 1.4692x over previous
#include <cuda_runtime.h>
#include <cuda_fp16.h>
#include <cstdint>
#include <cstddef>

// Problem: B=16, T=960, D=1024, W=10
#define DDIM  1024
#define WWIN  10
#define MTOT  15360          // B*T
#define KCONV 3072           // 3*D

static constexpr size_t XSZ = (size_t)MTOT * DDIM;
static constexpr size_t WSZ = (size_t)DDIM * KCONV;
static constexpr size_t GSZ = (size_t)DDIM * DDIM;

// Device scratch (allocation-free rules)
__device__ __half  g_x1[XSZ];      // x fp16, [m][c]
__device__ __half  g_w1[WSZ];      // conv w fp16, [n][k=s*1024+c]
__device__ __half  g_g1[GSZ];      // gate w fp16, [e][d]
__device__ __half  g_c1[XSZ];      // cnn fp16, [m][d]

// ------------------------------------------------------------------ PTX helpers
__device__ __forceinline__ uint32_t smem_u32(const void* p) {
    uint32_t a;
    asm("{ .reg .u64 t; cvta.to.shared.u64 t, %1; cvt.u32.u64 %0, t; }" : "=r"(a) : "l"(p));
    return a;
}
__device__ __forceinline__ void cp16(uint32_t dst, const void* src, uint32_t sz) {
    asm volatile("cp.async.cg.shared.global [%0], [%1], 16, %2;"
                 :: "r"(dst), "l"(src), "r"(sz) : "memory");
}
__device__ __forceinline__ void cp_commit() {
    asm volatile("cp.async.commit_group;" ::: "memory");
}
template <int N>
__device__ __forceinline__ void cp_wait() {
    asm volatile("cp.async.wait_group %0;" :: "n"(N) : "memory");
}
__device__ __forceinline__ void ldsm4(uint32_t* r, uint32_t addr) {
    asm volatile("ldmatrix.sync.aligned.m8n8.x4.shared.b16 {%0,%1,%2,%3}, [%4];"
                 : "=r"(r[0]), "=r"(r[1]), "=r"(r[2]), "=r"(r[3]) : "r"(addr));
}
__device__ __forceinline__ void mma16816(float* d, const uint32_t* a, const uint32_t* b) {
    asm volatile("mma.sync.aligned.m16n8k16.row.col.f32.f16.f16.f32 "
                 "{%0,%1,%2,%3}, {%4,%5,%6,%7}, {%8,%9}, {%0,%1,%2,%3};"
                 : "+f"(d[0]), "+f"(d[1]), "+f"(d[2]), "+f"(d[3])
                 : "r"(a[0]), "r"(a[1]), "r"(a[2]), "r"(a[3]), "r"(b[0]), "r"(b[1]));
}
__device__ __forceinline__ uint32_t pack_h2(float a, float b) {
    return (uint32_t)__half_as_ushort(__float2half_rn(a)) |
           ((uint32_t)__half_as_ushort(__float2half_rn(b)) << 16);
}

// ------------------------------------------------------------------ preprocessing
__global__ void k_split_x(const float* __restrict__ x) {
    size_t i = ((size_t)blockIdx.x * 256 + threadIdx.x) * 4;
    float4 v = *reinterpret_cast<const float4*>(x + i);
    uint2 uh;
    uh.x = pack_h2(v.x, v.y); uh.y = pack_h2(v.z, v.w);
    *reinterpret_cast<uint2*>(g_x1 + i) = uh;
}
__global__ void k_split_convw(const float* __restrict__ w) {
    size_t i = (size_t)blockIdx.x * 256 + threadIdx.x;   // over WSZ, out layout [n][s*1024+c]
    int n = (int)(i / KCONV);
    int k = (int)(i - (size_t)n * KCONV);
    int s = k >> 10, c = k & (DDIM - 1);
    g_w1[i] = __float2half_rn(w[(size_t)n * KCONV + c * 3 + s]);
}
__global__ void k_split_gatew(const float* __restrict__ gw) {
    size_t i = ((size_t)blockIdx.x * 256 + threadIdx.x) * 4;
    float4 v = *reinterpret_cast<const float4*>(gw + i);
    uint2 uh;
    uh.x = pack_h2(v.x, v.y); uh.y = pack_h2(v.z, v.w);
    *reinterpret_cast<uint2*>(g_g1 + i) = uh;
}

// ------------------------------------------------------------------ main GEMM
// CTA 128x128, BK=64 fp16. Stage [A 16KB | B 16KB] = 32KB; 3-stage ring = 96KB,
// occ 2. 8 warps in 4(M) x 2(N), warp tile 32x64.
// Inner loop: register double-buffered fragments (ks+1 ldsm overlaps ks MMAs).
static constexpr int PL_A = 0, PL_B = 16384;
static constexpr int STSZ = 32768;
static constexpr int SMEM_SZ = 3 * STSZ;   // 96 KB

template <int CHUNKS, bool IS_CONV>
__global__ __launch_bounds__(256, 2)
void k_mma(const float* __restrict__ bias, float* __restrict__ out) {
    extern __shared__ char smem[];
    const uint32_t sb = smem_u32(smem);

    const int tid = threadIdx.x;
    const int m0 = blockIdx.y * 128, n0 = blockIdx.x * 128;
    const int lane = tid & 31, w = tid >> 5;
    const int wm = w >> 1, wn = w & 1;          // warp grid 4(M) x 2(N)
    const int li = lane & 7, lg = lane >> 3;

    // loader geometry: thread -> (row lr, 4 of 8 16B sub-chunks)
    const int lr = tid >> 1;
    const int lh = (tid & 1) * 4;
    const int am = m0 + lr;
    const int amw = am % WWIN;

    auto load_chunk = [&](int c, int stage) {
        const uint32_t base = sb + stage * STSZ;
        const __half* Ap;
        const __half* Bp;
        uint32_t asz = 16;
        if (IS_CONV) {
            const int s = c >> 4, dt = s - 1, kc = (c & 15) << 6;
            const bool valid = ((unsigned)(amw + dt)) < (unsigned)WWIN;
            asz = valid ? 16u : 0u;
            Ap = g_x1 + (size_t)(valid ? (am + dt) : am) * DDIM + kc;
            Bp = g_w1 + (size_t)(n0 + lr) * KCONV + (c << 6);
        } else {
            Ap = g_c1 + (size_t)am * DDIM + (c << 6);
            Bp = g_g1 + (size_t)(n0 + lr) * DDIM + (c << 6);
        }
#pragma unroll
        for (int j = 0; j < 4; ++j) {
            const int cc = lh + j;
            const uint32_t d = base + lr * 128 + ((cc ^ (lr & 7)) * 16);
            cp16(d + PL_A, Ap + cc * 8, asz);
            cp16(d + PL_B, Bp + cc * 8, 16);
        }
        cp_commit();
    };

    float acc[2][8][4];
#pragma unroll
    for (int i = 0; i < 2; ++i)
#pragma unroll
        for (int j = 0; j < 8; ++j)
#pragma unroll
            for (int q = 0; q < 4; ++q) acc[i][j][q] = 0.f;

    uint32_t Bf[2][4][4];   // [buf][n16-tile][frag]
    uint32_t Af[2][2][4];   // [buf][m16-tile][frag]

    load_chunk(0, 0);
    if (CHUNKS > 1) load_chunk(1, 1);

    for (int it = 0; it < CHUNKS; ++it) {
        const int stage = it % 3;
        if (it + 1 < CHUNKS) cp_wait<1>(); else cp_wait<0>();
        __syncthreads();
        if (it + 2 < CHUNKS) load_chunk(it + 2, (it + 2) % 3);

        const uint32_t bb = sb + stage * STSZ;

        // fragment loads for a given ks into buffer fb
        auto ldB = [&](int ks, int fb) {
#pragma unroll
            for (int nt2 = 0; nt2 < 4; ++nt2) {
                const int br = wn * 64 + nt2 * 16 + li + (lg >> 1) * 8;
                const uint32_t cx = (uint32_t)((ks * 2 + (lg & 1)) ^ li);
                ldsm4(Bf[fb][nt2], bb + PL_B + br * 128 + cx * 16);
            }
        };
        auto ldA = [&](int ks, int fb) {
#pragma unroll
            for (int mt = 0; mt < 2; ++mt) {
                const int ar = wm * 32 + mt * 16 + li + (lg & 1) * 8;
                const uint32_t cx = (uint32_t)((ks * 2 + (lg >> 1)) ^ li);
                ldsm4(Af[fb][mt], bb + PL_A + ar * 128 + cx * 16);
            }
        };

        ldB(0, 0);
        ldA(0, 0);
#pragma unroll
        for (int ks = 0; ks < 4; ++ks) {
            const int cur = ks & 1;
            if (ks < 3) { ldB(ks + 1, cur ^ 1); ldA(ks + 1, cur ^ 1); }
#pragma unroll
            for (int mt = 0; mt < 2; ++mt) {
#pragma unroll
                for (int nt = 0; nt < 8; ++nt) {
                    const uint32_t b2[2] = {Bf[cur][nt >> 1][(nt & 1) * 2],
                                            Bf[cur][nt >> 1][(nt & 1) * 2 + 1]};
                    mma16816(acc[mt][nt], Af[cur][mt], b2);
                }
            }
        }
    }

    // ---- epilogue (direct from fragments; cnn kept in fp16 only)
#pragma unroll
    for (int mt = 0; mt < 2; ++mt) {
#pragma unroll
        for (int nt = 0; nt < 8; ++nt) {
            const int gn = n0 + wn * 64 + nt * 8 + (lane & 3) * 2;
            const float b0 = bias[gn], b1 = bias[gn + 1];
#pragma unroll
            for (int hh = 0; hh < 2; ++hh) {
                const int gm = m0 + wm * 32 + mt * 16 + (lane >> 2) + hh * 8;
                float v0 = acc[mt][nt][hh * 2 + 0] + b0;
                float v1 = acc[mt][nt][hh * 2 + 1] + b1;
                const size_t off = (size_t)gm * DDIM + gn;
                if (IS_CONV) {
                    *reinterpret_cast<uint32_t*>(g_c1 + off) = pack_h2(v0, v1);
                } else {
                    const __half2 ch = *reinterpret_cast<const __half2*>(g_c1 + off);
                    const float2 cv = __half22float2(ch);
                    float2 o;
                    o.x = cv.x * (1.f / (1.f + __expf(-v0)));
                    o.y = cv.y * (1.f / (1.f + __expf(-v1)));
                    *reinterpret_cast<float2*>(out + off) = o;
                }
            }
        }
    }
}

// ------------------------------------------------------------------ launch
extern "C" void kernel_launch(void* const* d_in, const int* in_sizes, int n_in,
                              void* d_out, int out_size) {
    const float* x      = (const float*)d_in[0];
    const float* conv_w = (const float*)d_in[1];
    const float* conv_b = (const float*)d_in[2];
    const float* gate_w = (const float*)d_in[3];
    const float* gate_b = (const float*)d_in[4];
    float* out = (float*)d_out;

    cudaFuncSetAttribute(k_mma<48, true>,  cudaFuncAttributeMaxDynamicSharedMemorySize, SMEM_SZ);
    cudaFuncSetAttribute(k_mma<16, false>, cudaFuncAttributeMaxDynamicSharedMemorySize, SMEM_SZ);

    k_split_x<<<(int)(XSZ / 1024), 256>>>(x);
    k_split_convw<<<(int)(WSZ / 256), 256>>>(conv_w);
    k_split_gatew<<<(int)(GSZ / 1024), 256>>>(gate_w);

    dim3 grid(DDIM / 128, MTOT / 128);   // (8, 120)
    k_mma<48, true><<<grid, 256, SMEM_SZ>>>(conv_b, nullptr);
    k_mma<16, false><<<grid, 256, SMEM_SZ>>>(gate_b, out);
}